// round 10
// baseline (speedup 1.0000x reference)
#include <cuda_runtime.h>

// CombinedLoraA: out[c, r] = sum_k x[xids[c*64+r], k] * A[wids[c], k, r]
//   x:[512,1,4096] f32  xids:[20480] i32  wids:[320] i32  A:[80,4096,64] f32
//   out:[320,1,64] f32
//
// R9: R3's measured-best main (256thr, lb(256,3) -> 85-reg budget, ASPLIT=7,
// KR=32 fp32 x-slice in smem w/ 8 XOR slot-groups, A in 32 regs, scratch STG)
// + in-CTA adapter grouping (kills 6.4us setup launch; R8's regression was
// the lb(512,2) 64-reg cap spilling the 80-reg working set, NOT grouping)
// + kr-parallel coalesced reduce (64 pairs x 4 kr-lanes, smem combine).

constexpr int KDIM   = 4096;
constexpr int RANK   = 64;
constexpr int CDIM   = 320;
constexpr int NADAPT = 80;
constexpr int NTOK   = 512;
constexpr int KR     = 32;               // k per range
constexpr int NKR    = KDIM / KR;        // 128
constexpr int ASPLIT = 7;                // grid 128*7 = 896 CTAs
constexpr int NTHR   = 256;
constexpr int NPAIR  = CDIM * RANK;      // 20480

constexpr int SMEM_BYTES = NTOK * KR * 4            // x slice (64 KB)
                         + CDIM * 4                 // perm
                         + CDIM * 4                 // wid
                         + (NADAPT + 1) * 4;        // seg  -> ~68.4 KB

__device__ float g_scratch[NKR * NPAIR];            // 10.5 MB k-partials

// ---- main: one CTA = (k-range, adapter-slot) ----
__global__ __launch_bounds__(NTHR, 3) void lora_main(
    const float* __restrict__ x,
    const int*   __restrict__ xids,
    const int*   __restrict__ wids,
    const float* __restrict__ A)
{
    extern __shared__ float smem[];
    float4* xs4    = reinterpret_cast<float4*>(smem);           // 512 rows x 8 f4 slots
    int*    perm_s = reinterpret_cast<int*>(smem + NTOK * KR);
    int*    wid_s  = perm_s + CDIM;
    int*    seg_s  = wid_s + CDIM;

    const int tid   = threadIdx.x;
    const int kr0   = blockIdx.x * KR;
    const int aslot = blockIdx.y;

    for (int i = tid; i < CDIM; i += NTHR) wid_s[i] = wids[i];

    // stage x k-range for ALL 512 rows; slot = k4 ^ (row & 7)
    for (int i = tid; i < NTOK * 8; i += NTHR) {
        const int row = i >> 3, k4 = i & 7;
        const float4 v = *reinterpret_cast<const float4*>(
            x + (size_t)row * KDIM + kr0 + k4 * 4);
        xs4[row * 8 + (k4 ^ (row & 7))] = v;
    }
    __syncthreads();   // wid_s ready (and x tile)

    // in-CTA adapter grouping: rank of (wid, c) -> perm; prefix counts -> seg
    for (int c = tid; c < CDIM; c += NTHR) {
        const int w = wid_s[c];
        int pos = 0;
#pragma unroll 8
        for (int c2 = 0; c2 < CDIM; ++c2) {
            const int w2 = wid_s[c2];
            pos += (w2 < w) || (w2 == w && c2 < c);
        }
        perm_s[pos] = c;
    }
    if (tid < NADAPT + 1) {
        int s = 0;
#pragma unroll 8
        for (int c2 = 0; c2 < CDIM; ++c2) s += (wid_s[c2] < tid);
        seg_s[tid] = s;
    }
    __syncthreads();

    const int r = tid & 63;          // rank index (lane-contiguous)
    const int g = tid >> 6;          // 4 independent thread-groups
    const int w_lo = (aslot * NADAPT) / ASPLIT;
    const int w_hi = ((aslot + 1) * NADAPT) / ASPLIT;

    float* __restrict__ scr = g_scratch + (size_t)blockIdx.x * NPAIR;

    for (int w = w_lo + g; w < w_hi; w += 4) {
        const int lo = seg_s[w], hi = seg_s[w + 1];
        if (lo >= hi) continue;

        // A[w, kr0..kr0+32, r] -> 32 registers (coalesced over r)
        float a[KR];
        const float* __restrict__ Ap = A + ((size_t)w * KDIM + kr0) * RANK + r;
#pragma unroll
        for (int j = 0; j < KR; ++j) a[j] = Ap[j * RANK];

        // software-pipelined token fetch (1 ahead)
        int ci = lo;
        int c  = perm_s[ci];
        int t  = xids[c * 64 + r];
        while (ci < hi) {
            const int c_cur = c, t_cur = t;
            ++ci;
            if (ci < hi) { c = perm_s[ci]; t = xids[c * 64 + r]; }

            const int s = t_cur & 7;
            const float4* __restrict__ xrow = xs4 + t_cur * 8;
            float acc0 = 0.f, acc1 = 0.f, acc2 = 0.f, acc3 = 0.f;
#pragma unroll
            for (int k4 = 0; k4 < 8; ++k4) {
                const float4 xv = xrow[k4 ^ s];
                acc0 = fmaf(a[k4 * 4 + 0], xv.x, acc0);
                acc1 = fmaf(a[k4 * 4 + 1], xv.y, acc1);
                acc2 = fmaf(a[k4 * 4 + 2], xv.z, acc2);
                acc3 = fmaf(a[k4 * 4 + 3], xv.w, acc3);
            }
            scr[c_cur * 64 + r] = (acc0 + acc1) + (acc2 + acc3);
        }
    }
}

// ---- reduce: 64 pairs x 4 kr-lanes per block, coalesced, smem combine ----
__global__ __launch_bounds__(256) void reduce_kernel(float* __restrict__ out)
{
    __shared__ float part[256];
    const int tid    = threadIdx.x;
    const int plocal = tid & 63;                  // pair within block
    const int klane  = tid >> 6;                  // 0..3 (warp-uniform -> coalesced)
    const int pair   = blockIdx.x * 64 + plocal;

    const float* __restrict__ base =
        g_scratch + (size_t)(klane * 32) * NPAIR + pair;

    float s0 = 0.f, s1 = 0.f, s2 = 0.f, s3 = 0.f;
    float s4 = 0.f, s5 = 0.f, s6 = 0.f, s7 = 0.f;
#pragma unroll
    for (int i = 0; i < 32; i += 8) {             // 32 partials per lane, MLP 8
        s0 += base[(size_t)(i + 0) * NPAIR];
        s1 += base[(size_t)(i + 1) * NPAIR];
        s2 += base[(size_t)(i + 2) * NPAIR];
        s3 += base[(size_t)(i + 3) * NPAIR];
        s4 += base[(size_t)(i + 4) * NPAIR];
        s5 += base[(size_t)(i + 5) * NPAIR];
        s6 += base[(size_t)(i + 6) * NPAIR];
        s7 += base[(size_t)(i + 7) * NPAIR];
    }
    part[klane * 64 + plocal] = ((s0 + s1) + (s2 + s3)) + ((s4 + s5) + (s6 + s7));
    __syncthreads();
    if (tid < 64)
        out[blockIdx.x * 64 + tid] =
            (part[tid] + part[64 + tid]) + (part[128 + tid] + part[192 + tid]);
}

extern "C" void kernel_launch(void* const* d_in, const int* in_sizes, int n_in,
                              void* d_out, int out_size)
{
    const float* x    = (const float*)d_in[0];
    const int*   xids = (const int*)  d_in[1];
    const int*   wids = (const int*)  d_in[2];
    const float* A    = (const float*)d_in[3];
    float*       out  = (float*)d_out;

    cudaFuncSetAttribute(lora_main,
                         cudaFuncAttributeMaxDynamicSharedMemorySize, SMEM_BYTES);

    lora_main<<<dim3(NKR, ASPLIT), NTHR, SMEM_BYTES>>>(x, xids, wids, A);
    reduce_kernel<<<NPAIR / 64, 256>>>(out);
}

// round 11
// speedup vs baseline: 1.9713x; 1.9713x over previous
#include <cuda_runtime.h>

// CombinedLoraA: out[c, r] = sum_k x[xids[c*64+r], k] * A[wids[c], k, r]
//   x:[512,1,4096] f32  xids:[20480] i32  wids:[320] i32  A:[80,4096,64] f32
//   out:[320,1,64] f32
//
// R10: three lean launches.
//   setup:  1 block, parallel brute-force rank -> g_perm/g_seg (~2-3us).
//           (R9's lesson: O(N^2) grouping per-CTA = ~50us of replicated ALU.)
//   main:   R3's measured-best 40.7us config, unchanged: per CTA (kr, aslot)
//           stage 32-k fp32 slice of all 512 x rows (8 XOR slot-groups),
//           A[w,kr,r] in 32 regs per thread, visit loop 8xLDS.128 + 32 FMA,
//           coalesced scratch STG.
//   reduce: 640 blocks, 8 kr-lanes x 32 pairs, MLP-16 per thread (~2.5us).

constexpr int KDIM   = 4096;
constexpr int RANK   = 64;
constexpr int CDIM   = 320;
constexpr int NADAPT = 80;
constexpr int NTOK   = 512;
constexpr int KR     = 32;               // k per range
constexpr int NKR    = KDIM / KR;        // 128
constexpr int ASPLIT = 7;                // grid 128*7 = 896 CTAs
constexpr int NTHR   = 256;
constexpr int NPAIR  = CDIM * RANK;      // 20480

constexpr int SMEM_BYTES = NTOK * KR * 4            // x slice (64 KB)
                         + CDIM * 4                 // perm
                         + (NADAPT + 1) * 4;        // seg  -> ~65.6 KB

__device__ float g_scratch[NKR * NPAIR];            // 10.5 MB k-partials
__device__ int   g_perm[CDIM];
__device__ int   g_seg[NADAPT + 1];

// ---- setup: ONE block, parallel brute-force rank (no serial scan) ----
__global__ __launch_bounds__(CDIM) void setup_kernel(const int* __restrict__ wids)
{
    __shared__ int wid_s[CDIM];
    const int tid = threadIdx.x;          // 0..319
    wid_s[tid] = wids[tid];
    __syncthreads();

    const int w = wid_s[tid];
    int pos = 0;
#pragma unroll 16
    for (int c2 = 0; c2 < CDIM; ++c2) {
        const int w2 = wid_s[c2];
        pos += (w2 < w) || (w2 == w && c2 < tid);
    }
    g_perm[pos] = tid;

    if (tid < NADAPT + 1) {
        int s = 0;
#pragma unroll 16
        for (int c2 = 0; c2 < CDIM; ++c2) s += (wid_s[c2] < tid);
        g_seg[tid] = s;
    }
}

// ---- main: one CTA = (k-range, adapter-slot) ----
__global__ __launch_bounds__(NTHR, 3) void lora_main(
    const float* __restrict__ x,
    const int*   __restrict__ xids,
    const float* __restrict__ A)
{
    extern __shared__ float smem[];
    float4* xs4    = reinterpret_cast<float4*>(smem);           // 512 rows x 8 f4 slots
    int*    perm_s = reinterpret_cast<int*>(smem + NTOK * KR);
    int*    seg_s  = perm_s + CDIM;

    const int tid   = threadIdx.x;
    const int kr0   = blockIdx.x * KR;
    const int aslot = blockIdx.y;

    // stage x k-range for ALL 512 rows; slot = k4 ^ (row & 7)
    for (int i = tid; i < NTOK * 8; i += NTHR) {
        const int row = i >> 3, k4 = i & 7;
        const float4 v = *reinterpret_cast<const float4*>(
            x + (size_t)row * KDIM + kr0 + k4 * 4);
        xs4[row * 8 + (k4 ^ (row & 7))] = v;
    }
    for (int i = tid; i < CDIM; i += NTHR)       perm_s[i] = g_perm[i];
    for (int i = tid; i < NADAPT + 1; i += NTHR) seg_s[i]  = g_seg[i];
    __syncthreads();

    const int r = tid & 63;          // rank index (lane-contiguous)
    const int g = tid >> 6;          // 4 independent thread-groups
    const int w_lo = (aslot * NADAPT) / ASPLIT;
    const int w_hi = ((aslot + 1) * NADAPT) / ASPLIT;

    float* __restrict__ scr = g_scratch + (size_t)blockIdx.x * NPAIR;

    for (int w = w_lo + g; w < w_hi; w += 4) {
        const int lo = seg_s[w], hi = seg_s[w + 1];
        if (lo >= hi) continue;

        // A[w, kr0..kr0+32, r] -> 32 registers (coalesced over r)
        float a[KR];
        const float* __restrict__ Ap = A + ((size_t)w * KDIM + kr0) * RANK + r;
#pragma unroll
        for (int j = 0; j < KR; ++j) a[j] = Ap[j * RANK];

        // software-pipelined token fetch (1 ahead)
        int ci = lo;
        int c  = perm_s[ci];
        int t  = xids[c * 64 + r];
        while (ci < hi) {
            const int c_cur = c, t_cur = t;
            ++ci;
            if (ci < hi) { c = perm_s[ci]; t = xids[c * 64 + r]; }

            const int s = t_cur & 7;
            const float4* __restrict__ xrow = xs4 + t_cur * 8;
            float acc0 = 0.f, acc1 = 0.f, acc2 = 0.f, acc3 = 0.f;
#pragma unroll
            for (int k4 = 0; k4 < 8; ++k4) {
                const float4 xv = xrow[k4 ^ s];
                acc0 = fmaf(a[k4 * 4 + 0], xv.x, acc0);
                acc1 = fmaf(a[k4 * 4 + 1], xv.y, acc1);
                acc2 = fmaf(a[k4 * 4 + 2], xv.z, acc2);
                acc3 = fmaf(a[k4 * 4 + 3], xv.w, acc3);
            }
            scr[c_cur * 64 + r] = (acc0 + acc1) + (acc2 + acc3);
        }
    }
}

// ---- reduce: 640 blocks; block = 8 kr-lanes x 32 pairs; MLP-16/thread ----
__global__ __launch_bounds__(256) void reduce_kernel(float* __restrict__ out)
{
    __shared__ float part[256];
    const int tid    = threadIdx.x;
    const int plocal = tid & 31;                  // pair within block
    const int klane  = tid >> 5;                  // 0..7 (warp-uniform)
    const int pair   = blockIdx.x * 32 + plocal;

    const float* __restrict__ base =
        g_scratch + (size_t)(klane * 16) * NPAIR + pair;

    float s[16];
#pragma unroll
    for (int i = 0; i < 16; ++i) s[i] = base[(size_t)i * NPAIR];   // MLP 16
    float t0 = ((s[0]+s[1])+(s[2]+s[3])) + ((s[4]+s[5])+(s[6]+s[7]));
    float t1 = ((s[8]+s[9])+(s[10]+s[11])) + ((s[12]+s[13])+(s[14]+s[15]));
    part[klane * 32 + plocal] = t0 + t1;
    __syncthreads();
    if (tid < 32) {
        float r0 = part[tid]       + part[32 + tid];
        float r1 = part[64 + tid]  + part[96 + tid];
        float r2 = part[128 + tid] + part[160 + tid];
        float r3 = part[192 + tid] + part[224 + tid];
        out[blockIdx.x * 32 + tid] = (r0 + r1) + (r2 + r3);
    }
}

extern "C" void kernel_launch(void* const* d_in, const int* in_sizes, int n_in,
                              void* d_out, int out_size)
{
    const float* x    = (const float*)d_in[0];
    const int*   xids = (const int*)  d_in[1];
    const int*   wids = (const int*)  d_in[2];
    const float* A    = (const float*)d_in[3];
    float*       out  = (float*)d_out;

    cudaFuncSetAttribute(lora_main,
                         cudaFuncAttributeMaxDynamicSharedMemorySize, SMEM_BYTES);

    setup_kernel<<<1, CDIM>>>(wids);
    lora_main<<<dim3(NKR, ASPLIT), NTHR, SMEM_BYTES>>>(x, xids, A);
    reduce_kernel<<<NPAIR / 32, 256>>>(out);
}